// round 1
// baseline (speedup 1.0000x reference)
#include <cuda_runtime.h>
#include <math.h>

#define NTOK 4096
#define DMODEL 1024
#define DHID 4096
#define NEXP 8

// ---- scratch (device globals: allocation-free) ----
__device__ int   g_expert[NTOK];
__device__ float g_gatew[NTOK];
__device__ int   g_counts[NEXP];
__device__ int   g_offsets[NEXP + 1];
__device__ int   g_cursor[NEXP];
__device__ int   g_perm[NTOK];                    // slot -> token
__device__ float g_h[(size_t)NTOK * DHID];        // grouped hidden activations (64 MB)

// ---- K0: zero counters ----
__global__ void k_zero() {
    int t = threadIdx.x;
    if (t < NEXP) { g_counts[t] = 0; g_cursor[t] = 0; }
}

// ---- K1: gating (one warp per token) ----
__global__ void k_gate(const float* __restrict__ x,
                       const float* __restrict__ Wg,
                       const float* __restrict__ bg) {
    int tok  = blockIdx.x * 8 + (threadIdx.x >> 5);
    int lane = threadIdx.x & 31;
    if (tok >= NTOK) return;

    float acc[NEXP];
#pragma unroll
    for (int e = 0; e < NEXP; e++) acc[e] = 0.f;

    const float* xr = x + (size_t)tok * DMODEL;
    for (int d = lane; d < DMODEL; d += 32) {
        float xv = xr[d];
        const float* wr = Wg + d * NEXP;
#pragma unroll
        for (int e = 0; e < NEXP; e++) acc[e] += xv * wr[e];
    }
#pragma unroll
    for (int e = 0; e < NEXP; e++) {
#pragma unroll
        for (int o = 16; o > 0; o >>= 1)
            acc[e] += __shfl_xor_sync(0xffffffffu, acc[e], o);
    }
    if (lane == 0) {
        float m = -1e30f; int arg = 0;
#pragma unroll
        for (int e = 0; e < NEXP; e++) {
            float l = acc[e] + bg[e];
            acc[e] = l;
            if (l > m) { m = l; arg = e; }   // strict > keeps first index (jnp.argmax)
        }
        float s = 0.f;
#pragma unroll
        for (int e = 0; e < NEXP; e++) s += expf(acc[e] - m);
        g_expert[tok] = arg;
        g_gatew[tok]  = 1.0f / s;            // softmax prob of argmax
        atomicAdd(&g_counts[arg], 1);
    }
}

// ---- K2: exclusive scan (tiny) ----
__global__ void k_scan() {
    if (threadIdx.x == 0) {
        int acc = 0;
        g_offsets[0] = 0;
        for (int e = 0; e < NEXP; e++) {
            acc += g_counts[e];
            g_offsets[e + 1] = acc;
            g_cursor[e] = g_offsets[e];
        }
    }
}

// ---- K3: scatter tokens into per-expert slots ----
__global__ void k_scatter() {
    int tok = blockIdx.x * blockDim.x + threadIdx.x;
    if (tok >= NTOK) return;
    int e = g_expert[tok];
    int slot = atomicAdd(&g_cursor[e], 1);
    g_perm[slot] = tok;
}

// ---- GEMM tiling ----
#define BM 128
#define BN 128
#define BK 16

// ---- K4: h = silu(x_gathered @ W1[e] + b1[e]) ----
__global__ __launch_bounds__(256) void k_ffn1(const float* __restrict__ x,
                                              const float* __restrict__ W1,
                                              const float* __restrict__ b1) {
    int e    = blockIdx.z;
    int off  = g_offsets[e];
    int cnt  = g_offsets[e + 1] - off;
    int row0 = blockIdx.y * BM;
    if (row0 >= cnt) return;
    int col0 = blockIdx.x * BN;

    __shared__ float As[BK][BM + 4];   // transposed A tile (row stride 132 floats = 528B, 16B-aligned)
    __shared__ float Bs[BK][BN];

    int tid = threadIdx.x;
    int ty = tid >> 4, tx = tid & 15;

    // resolve gathered token rows for the two A-load slots of this thread
    const float* aptr[2];
#pragma unroll
    for (int r = 0; r < 2; r++) {
        int s = tid + r * 256;
        int i = s >> 2;
        int li = row0 + i;
        int tok = (li < cnt) ? g_perm[off + li] : g_perm[off];   // safe clamp
        aptr[r] = x + (size_t)tok * DMODEL;
    }
    const float* Bbase = W1 + (size_t)e * DMODEL * DHID + col0;

    float acc[8][8] = {};

    for (int k0 = 0; k0 < DMODEL; k0 += BK) {
#pragma unroll
        for (int r = 0; r < 2; r++) {
            int s = tid + r * 256;
            int i = s >> 2, k4 = (s & 3) * 4;
            float4 v = *(const float4*)(aptr[r] + k0 + k4);
            As[k4 + 0][i] = v.x; As[k4 + 1][i] = v.y;
            As[k4 + 2][i] = v.z; As[k4 + 3][i] = v.w;
        }
#pragma unroll
        for (int r = 0; r < 2; r++) {
            int s = tid + r * 256;
            int k = s >> 5, j4 = (s & 31) * 4;
            *(float4*)&Bs[k][j4] = *(const float4*)(Bbase + (size_t)(k0 + k) * DHID + j4);
        }
        __syncthreads();
#pragma unroll
        for (int kk = 0; kk < BK; kk++) {
            float a[8], b[8];
            *(float4*)&a[0] = *(const float4*)&As[kk][ty * 8];
            *(float4*)&a[4] = *(const float4*)&As[kk][ty * 8 + 4];
            *(float4*)&b[0] = *(const float4*)&Bs[kk][tx * 8];
            *(float4*)&b[4] = *(const float4*)&Bs[kk][tx * 8 + 4];
#pragma unroll
            for (int i = 0; i < 8; i++)
#pragma unroll
                for (int j = 0; j < 8; j++)
                    acc[i][j] += a[i] * b[j];
        }
        __syncthreads();
    }

    const float* b1e = b1 + (size_t)e * DHID + col0;
#pragma unroll
    for (int i = 0; i < 8; i++) {
        int li = row0 + ty * 8 + i;
        if (li >= cnt) continue;
        float* hrow = g_h + (size_t)(off + li) * DHID + col0;
#pragma unroll
        for (int j = 0; j < 8; j++) {
            int c = tx * 8 + j;
            float z = acc[i][j] + b1e[c];
            hrow[c] = z / (1.f + expf(-z));     // silu
        }
    }
}

// ---- K5: y[tok] = (h_grouped @ W2[e] + b2[e]) * gate_w ----
__global__ __launch_bounds__(256) void k_ffn2(const float* __restrict__ W2,
                                              const float* __restrict__ b2,
                                              float* __restrict__ y) {
    int e    = blockIdx.z;
    int off  = g_offsets[e];
    int cnt  = g_offsets[e + 1] - off;
    int row0 = blockIdx.y * BM;
    if (row0 >= cnt) return;
    int col0 = blockIdx.x * BN;

    __shared__ float As[BK][BM + 4];
    __shared__ float Bs[BK][BN];

    int tid = threadIdx.x;
    int ty = tid >> 4, tx = tid & 15;

    const float* aptr[2];
#pragma unroll
    for (int r = 0; r < 2; r++) {
        int s = tid + r * 256;
        int i = s >> 2;
        int li = row0 + i;
        if (li >= cnt) li = cnt - 1;                    // clamp: row exists (row0<cnt)
        aptr[r] = g_h + (size_t)(off + li) * DHID;
    }
    const float* Bbase = W2 + (size_t)e * DHID * DMODEL + col0;

    float acc[8][8] = {};

    for (int k0 = 0; k0 < DHID; k0 += BK) {
#pragma unroll
        for (int r = 0; r < 2; r++) {
            int s = tid + r * 256;
            int i = s >> 2, k4 = (s & 3) * 4;
            float4 v = *(const float4*)(aptr[r] + k0 + k4);
            As[k4 + 0][i] = v.x; As[k4 + 1][i] = v.y;
            As[k4 + 2][i] = v.z; As[k4 + 3][i] = v.w;
        }
#pragma unroll
        for (int r = 0; r < 2; r++) {
            int s = tid + r * 256;
            int k = s >> 5, j4 = (s & 31) * 4;
            *(float4*)&Bs[k][j4] = *(const float4*)(Bbase + (size_t)(k0 + k) * DMODEL + j4);
        }
        __syncthreads();
#pragma unroll
        for (int kk = 0; kk < BK; kk++) {
            float a[8], b[8];
            *(float4*)&a[0] = *(const float4*)&As[kk][ty * 8];
            *(float4*)&a[4] = *(const float4*)&As[kk][ty * 8 + 4];
            *(float4*)&b[0] = *(const float4*)&Bs[kk][tx * 8];
            *(float4*)&b[4] = *(const float4*)&Bs[kk][tx * 8 + 4];
#pragma unroll
            for (int i = 0; i < 8; i++)
#pragma unroll
                for (int j = 0; j < 8; j++)
                    acc[i][j] += a[i] * b[j];
        }
        __syncthreads();
    }

    const float* b2e = b2 + (size_t)e * DMODEL + col0;
#pragma unroll
    for (int i = 0; i < 8; i++) {
        int li = row0 + ty * 8 + i;
        if (li >= cnt) continue;
        int tok = g_perm[off + li];
        float w = g_gatew[tok];
        float* yrow = y + (size_t)tok * DMODEL + col0;
#pragma unroll
        for (int j = 0; j < 8; j++) {
            int c = tx * 8 + j;
            yrow[c] = (acc[i][j] + b2e[c]) * w;
        }
    }
}

extern "C" void kernel_launch(void* const* d_in, const int* in_sizes, int n_in,
                              void* d_out, int out_size) {
    const float* x  = (const float*)d_in[0];
    const float* Wg = (const float*)d_in[1];
    const float* bg = (const float*)d_in[2];
    const float* W1 = (const float*)d_in[3];
    const float* b1 = (const float*)d_in[4];
    const float* W2 = (const float*)d_in[5];
    const float* b2 = (const float*)d_in[6];
    float* y = (float*)d_out;

    k_zero<<<1, 32>>>();
    k_gate<<<NTOK / 8, 256>>>(x, Wg, bg);
    k_scan<<<1, 1>>>();
    k_scatter<<<NTOK / 256, 256>>>();
    k_ffn1<<<dim3(DHID / BN, NTOK / BM, NEXP), 256>>>(x, W1, b1);
    k_ffn2<<<dim3(DMODEL / BN, NTOK / BM, NEXP), 256>>>(W2, b2, y);
}

// round 6
// speedup vs baseline: 1.7387x; 1.7387x over previous
#include <cuda_runtime.h>
#include <cuda_bf16.h>
#include <math.h>
#include <stdint.h>

#define NTOK 4096
#define DMODEL 1024
#define DHID 4096
#define NEXP 8

// ================= scratch (device globals: allocation-free) =================
__device__ int   g_expert[NTOK];
__device__ float g_gatew[NTOK];
__device__ int   g_counts[NEXP];
__device__ int   g_offsets[NEXP + 1];
__device__ int   g_cursor[NEXP];
__device__ int   g_perm[NTOK];
__device__ __align__(256) float g_h[(size_t)NTOK * DHID];   // grouped hidden (fp32, 64MB)

__device__ __forceinline__ void mma16816(float* d, const uint32_t* a, uint32_t b0, uint32_t b1) {
    asm volatile("mma.sync.aligned.m16n8k16.row.col.f32.bf16.bf16.f32 "
        "{%0,%1,%2,%3}, {%4,%5,%6,%7}, {%8,%9}, {%0,%1,%2,%3};"
        : "+f"(d[0]), "+f"(d[1]), "+f"(d[2]), "+f"(d[3])
        : "r"(a[0]), "r"(a[1]), "r"(a[2]), "r"(a[3]), "r"(b0), "r"(b1));
}

// split fp32 -> (hi,lo) bf16 pair packed as bf16x2 words (low half = even element)
__device__ __forceinline__ void split2(float f0, float f1, uint32_t& hi, uint32_t& lo) {
    __nv_bfloat16 h0 = __float2bfloat16_rn(f0);
    __nv_bfloat16 h1 = __float2bfloat16_rn(f1);
    __nv_bfloat16 l0 = __float2bfloat16_rn(f0 - __bfloat162float(h0));
    __nv_bfloat16 l1 = __float2bfloat16_rn(f1 - __bfloat162float(h1));
    hi = (uint32_t)__bfloat16_as_ushort(h0) | ((uint32_t)__bfloat16_as_ushort(h1) << 16);
    lo = (uint32_t)__bfloat16_as_ushort(l0) | ((uint32_t)__bfloat16_as_ushort(l1) << 16);
}

// ================= gating / routing (R1-proven) =================
__global__ void k_zero() {
    int t = threadIdx.x;
    if (t < NEXP) { g_counts[t] = 0; g_cursor[t] = 0; }
}
__global__ void k_gate(const float* __restrict__ x, const float* __restrict__ Wg,
                       const float* __restrict__ bg) {
    int tok = blockIdx.x * 8 + (threadIdx.x >> 5);
    int lane = threadIdx.x & 31;
    if (tok >= NTOK) return;
    float acc[NEXP];
#pragma unroll
    for (int e = 0; e < NEXP; e++) acc[e] = 0.f;
    const float* xr = x + (size_t)tok * DMODEL;
    for (int d = lane; d < DMODEL; d += 32) {
        float xv = xr[d];
        const float* wr = Wg + d * NEXP;
#pragma unroll
        for (int e = 0; e < NEXP; e++) acc[e] += xv * wr[e];
    }
#pragma unroll
    for (int e = 0; e < NEXP; e++)
#pragma unroll
        for (int o = 16; o > 0; o >>= 1) acc[e] += __shfl_xor_sync(0xffffffffu, acc[e], o);
    if (lane == 0) {
        float m = -1e30f; int arg = 0;
#pragma unroll
        for (int e = 0; e < NEXP; e++) {
            float l = acc[e] + bg[e]; acc[e] = l;
            if (l > m) { m = l; arg = e; }   // strict > : first-index argmax like jnp
        }
        float s = 0.f;
#pragma unroll
        for (int e = 0; e < NEXP; e++) s += expf(acc[e] - m);
        g_expert[tok] = arg;
        g_gatew[tok] = 1.0f / s;
        atomicAdd(&g_counts[arg], 1);
    }
}
__global__ void k_scan() {
    if (threadIdx.x == 0) {
        int acc = 0; g_offsets[0] = 0;
        for (int e = 0; e < NEXP; e++) {
            acc += g_counts[e];
            g_offsets[e + 1] = acc;
            g_cursor[e] = g_offsets[e];
        }
    }
}
__global__ void k_scatter() {
    int tok = blockIdx.x * blockDim.x + threadIdx.x;
    if (tok >= NTOK) return;
    int slot = atomicAdd(&g_cursor[g_expert[tok]], 1);
    g_perm[slot] = tok;
}

// ================= HMMA grouped GEMM, on-the-fly bf16 hi/lo split =================
// BM=128, BN=128, BK=32 (fp32 sources). Smem: 4 bf16 tiles (A_hi,A_lo,B_hi,B_lo),
// 80B padded rows, 40KB static. Register-prefetch double buffering.
// Per k-tile: acc += Ahi*Bhi + Alo*Bhi + Ahi*Blo  (error-compensated bf16 product).
// 8 warps (4M x 2N), warp tile 32x64, mma.sync.m16n8k16.
#define ROWB 80
#define AHI 0
#define ALO 10240
#define BHI 20480
#define BLO 30720

template <bool IS2>
__global__ __launch_bounds__(256) void k_ffn_mma(const float* __restrict__ W,
                                                 const float* __restrict__ bias,
                                                 const float* __restrict__ x,
                                                 float* __restrict__ y) {
    constexpr int K  = IS2 ? DHID : DMODEL;
    constexpr int NN = IS2 ? DMODEL : DHID;
    constexpr int KT = K / 32;

    __shared__ __align__(16) char smemc[40960];

    int e = blockIdx.z;
    int off = g_offsets[e];
    int cnt = g_offsets[e + 1] - off;
    int row0 = blockIdx.y * 128;
    if (row0 >= cnt) return;
    int col0 = blockIdx.x * 128;

    int tid = threadIdx.x, lane = tid & 31, wid = tid >> 5;
    int wm = wid & 3, wn = wid >> 2;
    int g = lane >> 2, q = lane & 3;

    // ---- per-thread staging assignments ----
    // A: c = tid + 256t -> row = c>>3 (128 rows), c8 = c&7 (8 float4 per 32-float row)
    const float* arow[4]; uint32_t asw[4];
    // B: c -> n = c&127, k4 = c>>7 (8 groups of 4 k)
    const float* brow[4]; uint32_t bsw[4];
#pragma unroll
    for (int t = 0; t < 4; t++) {
        int c = tid + t * 256;
        int row = c >> 3, c8 = c & 7;
        int slot = off + row0 + row; if (slot > NTOK - 1) slot = NTOK - 1;
        if (IS2) arow[t] = g_h + (size_t)slot * DHID + c8 * 4;
        else     arow[t] = x + (size_t)g_perm[slot] * DMODEL + c8 * 4;
        asw[t] = (uint32_t)(row * ROWB + c8 * 8);
        int n = c & 127, k4 = c >> 7;
        brow[t] = W + (size_t)e * K * NN + (size_t)(k4 * 4) * NN + col0 + n;
        bsw[t] = (uint32_t)(n * ROWB + k4 * 8);
    }

    float acc[2][8][4];
#pragma unroll
    for (int i = 0; i < 2; i++)
#pragma unroll
        for (int j = 0; j < 8; j++)
#pragma unroll
            for (int p = 0; p < 4; p++) acc[i][j][p] = 0.f;

    float4 fa[4];
    float fb[4][4];
    // prefetch k-tile 0
#pragma unroll
    for (int t = 0; t < 4; t++) {
        fa[t] = *(const float4*)(arow[t]);
#pragma unroll
        for (int j = 0; j < 4; j++) fb[t][j] = brow[t][(size_t)j * NN];
    }

    for (int kt = 0; kt < KT; kt++) {
        __syncthreads();   // previous compute done before overwriting smem
        // ---- store staged tile (split fp32 -> hi/lo bf16) ----
#pragma unroll
        for (int t = 0; t < 4; t++) {
            uint32_t h0, l0, h1, l1;
            split2(fa[t].x, fa[t].y, h0, l0);
            split2(fa[t].z, fa[t].w, h1, l1);
            uint2 u;
            u.x = h0; u.y = h1; *(uint2*)(smemc + AHI + asw[t]) = u;
            u.x = l0; u.y = l1; *(uint2*)(smemc + ALO + asw[t]) = u;
            split2(fb[t][0], fb[t][1], h0, l0);
            split2(fb[t][2], fb[t][3], h1, l1);
            u.x = h0; u.y = h1; *(uint2*)(smemc + BHI + bsw[t]) = u;
            u.x = l0; u.y = l1; *(uint2*)(smemc + BLO + bsw[t]) = u;
        }
        __syncthreads();
        // ---- prefetch next k-tile ----
        if (kt + 1 < KT) {
            int kk = (kt + 1) * 32;
#pragma unroll
            for (int t = 0; t < 4; t++) {
                fa[t] = *(const float4*)(arow[t] + kk);
#pragma unroll
                for (int j = 0; j < 4; j++) fb[t][j] = brow[t][(size_t)(kk + j) * NN];
            }
        }
        // ---- compute ----
#pragma unroll
        for (int k16 = 0; k16 < 2; k16++) {
            uint32_t koff = (uint32_t)(k16 * 32 + q * 4);
            uint32_t ah[2][4], al[2][4];
#pragma unroll
            for (int mt = 0; mt < 2; mt++) {
                uint32_t ab = (uint32_t)((wm * 32 + mt * 16 + g) * ROWB) + koff;
                ah[mt][0] = *(const uint32_t*)(smemc + AHI + ab);
                ah[mt][1] = *(const uint32_t*)(smemc + AHI + ab + 8 * ROWB);
                ah[mt][2] = *(const uint32_t*)(smemc + AHI + ab + 16);
                ah[mt][3] = *(const uint32_t*)(smemc + AHI + ab + 8 * ROWB + 16);
                al[mt][0] = *(const uint32_t*)(smemc + ALO + ab);
                al[mt][1] = *(const uint32_t*)(smemc + ALO + ab + 8 * ROWB);
                al[mt][2] = *(const uint32_t*)(smemc + ALO + ab + 16);
                al[mt][3] = *(const uint32_t*)(smemc + ALO + ab + 8 * ROWB + 16);
            }
#pragma unroll
            for (int nt8 = 0; nt8 < 8; nt8++) {
                uint32_t bb = (uint32_t)((wn * 64 + nt8 * 8 + g) * ROWB) + koff;
                uint32_t bh0 = *(const uint32_t*)(smemc + BHI + bb);
                uint32_t bh1 = *(const uint32_t*)(smemc + BHI + bb + 16);
                uint32_t bl0 = *(const uint32_t*)(smemc + BLO + bb);
                uint32_t bl1 = *(const uint32_t*)(smemc + BLO + bb + 16);
                mma16816(acc[0][nt8], ah[0], bh0, bh1);
                mma16816(acc[1][nt8], ah[1], bh0, bh1);
                mma16816(acc[0][nt8], al[0], bh0, bh1);
                mma16816(acc[1][nt8], al[1], bh0, bh1);
                mma16816(acc[0][nt8], ah[0], bl0, bl1);
                mma16816(acc[1][nt8], ah[1], bl0, bl1);
            }
        }
    }

    // ================= epilogue =================
    const float* be_ = bias + (size_t)e * NN;
    int q2 = q * 2;
#pragma unroll
    for (int mt = 0; mt < 2; mt++) {
#pragma unroll
        for (int half = 0; half < 2; half++) {
            int ml = wm * 32 + mt * 16 + g + half * 8;
            if (row0 + ml >= cnt) continue;
            int slot = off + row0 + ml;
            if (!IS2) {
                float* hrow = g_h + (size_t)slot * DHID;
#pragma unroll
                for (int nt8 = 0; nt8 < 8; nt8++) {
                    int cg = col0 + wn * 64 + nt8 * 8 + q2;
                    float z0 = acc[mt][nt8][half * 2 + 0] + be_[cg];
                    float z1 = acc[mt][nt8][half * 2 + 1] + be_[cg + 1];
                    float2 o;
                    o.x = z0 / (1.f + expf(-z0));
                    o.y = z1 / (1.f + expf(-z1));
                    *(float2*)(hrow + cg) = o;
                }
            } else {
                int tok = g_perm[slot];
                float gw = g_gatew[tok];
                float* yrow = y + (size_t)tok * DMODEL;
#pragma unroll
                for (int nt8 = 0; nt8 < 8; nt8++) {
                    int cg = col0 + wn * 64 + nt8 * 8 + q2;
                    float2 o;
                    o.x = (acc[mt][nt8][half * 2 + 0] + be_[cg]) * gw;
                    o.y = (acc[mt][nt8][half * 2 + 1] + be_[cg + 1]) * gw;
                    *(float2*)(yrow + cg) = o;
                }
            }
        }
    }
}

// ================= launch =================
extern "C" void kernel_launch(void* const* d_in, const int* in_sizes, int n_in,
                              void* d_out, int out_size) {
    const float* x  = (const float*)d_in[0];
    const float* Wg = (const float*)d_in[1];
    const float* bg = (const float*)d_in[2];
    const float* W1 = (const float*)d_in[3];
    const float* b1 = (const float*)d_in[4];
    const float* W2 = (const float*)d_in[5];
    const float* b2 = (const float*)d_in[6];
    float* y = (float*)d_out;

    k_zero<<<1, 32>>>();
    k_gate<<<NTOK / 8, 256>>>(x, Wg, bg);
    k_scan<<<1, 1>>>();
    k_scatter<<<NTOK / 256, 256>>>();
    k_ffn_mma<false><<<dim3(DHID / 128, NTOK / 128, NEXP), 256>>>(W1, b1, x, nullptr);
    k_ffn_mma<true ><<<dim3(DMODEL / 128, NTOK / 128, NEXP), 256>>>(W2, b2, x, y);
}

// round 7
// speedup vs baseline: 2.1586x; 1.2415x over previous
#include <cuda_runtime.h>
#include <cuda_bf16.h>
#include <math.h>
#include <stdint.h>

#define NTOK 4096
#define DMODEL 1024
#define DHID 4096
#define NEXP 8

// ================= scratch (device globals: allocation-free) =================
__device__ int   g_expert[NTOK];
__device__ float g_gatew[NTOK];
__device__ int   g_counts[NEXP];
__device__ int   g_offsets[NEXP + 1];
__device__ int   g_cursor[NEXP];
__device__ int   g_perm[NTOK];
__device__ __align__(256) float g_h[(size_t)NTOK * DHID];   // grouped hidden (fp32, 64MB)

__device__ __forceinline__ uint32_t smem_u32(const void* p) {
    uint32_t a;
    asm("{ .reg .u64 t; cvta.to.shared.u64 t, %1; cvt.u32.u64 %0, t; }" : "=r"(a) : "l"(p));
    return a;
}
__device__ __forceinline__ void mma16816(float* d, const uint32_t* a, uint32_t b0, uint32_t b1) {
    asm volatile("mma.sync.aligned.m16n8k16.row.col.f32.bf16.bf16.f32 "
        "{%0,%1,%2,%3}, {%4,%5,%6,%7}, {%8,%9}, {%0,%1,%2,%3};"
        : "+f"(d[0]), "+f"(d[1]), "+f"(d[2]), "+f"(d[3])
        : "r"(a[0]), "r"(a[1]), "r"(a[2]), "r"(a[3]), "r"(b0), "r"(b1));
}
__device__ __forceinline__ void ldsm_x4(uint32_t a, uint32_t& r0, uint32_t& r1,
                                        uint32_t& r2, uint32_t& r3) {
    asm volatile("ldmatrix.sync.aligned.m8n8.x4.shared.b16 {%0,%1,%2,%3}, [%4];"
        : "=r"(r0), "=r"(r1), "=r"(r2), "=r"(r3) : "r"(a));
}

// fast split: hi = truncate-to-bf16 (bit ops), lo = exact residual, RN to bf16x2.
// packed words have even element in low half.
__device__ __forceinline__ void split2(float f0, float f1, uint32_t& hi, uint32_t& lo) {
    uint32_t u0 = __float_as_uint(f0), u1 = __float_as_uint(f1);
    hi = __byte_perm(u0, u1, 0x7632);
    float r0 = f0 - __uint_as_float(u0 & 0xFFFF0000u);
    float r1 = f1 - __uint_as_float(u1 & 0xFFFF0000u);
    __nv_bfloat162 p = __floats2bfloat162_rn(r0, r1);   // x (=r0) in low half
    lo = *(uint32_t*)&p;
}

// ================= gating / routing (R1-proven) =================
__global__ void k_zero() {
    int t = threadIdx.x;
    if (t < NEXP) { g_counts[t] = 0; g_cursor[t] = 0; }
}
__global__ void k_gate(const float* __restrict__ x, const float* __restrict__ Wg,
                       const float* __restrict__ bg) {
    int tok = blockIdx.x * 8 + (threadIdx.x >> 5);
    int lane = threadIdx.x & 31;
    if (tok >= NTOK) return;
    float acc[NEXP];
#pragma unroll
    for (int e = 0; e < NEXP; e++) acc[e] = 0.f;
    const float* xr = x + (size_t)tok * DMODEL;
    for (int d = lane; d < DMODEL; d += 32) {
        float xv = xr[d];
        const float* wr = Wg + d * NEXP;
#pragma unroll
        for (int e = 0; e < NEXP; e++) acc[e] += xv * wr[e];
    }
#pragma unroll
    for (int e = 0; e < NEXP; e++)
#pragma unroll
        for (int o = 16; o > 0; o >>= 1) acc[e] += __shfl_xor_sync(0xffffffffu, acc[e], o);
    if (lane == 0) {
        float m = -1e30f; int arg = 0;
#pragma unroll
        for (int e = 0; e < NEXP; e++) {
            float l = acc[e] + bg[e]; acc[e] = l;
            if (l > m) { m = l; arg = e; }   // strict > : first-index argmax like jnp
        }
        float s = 0.f;
#pragma unroll
        for (int e = 0; e < NEXP; e++) s += expf(acc[e] - m);
        g_expert[tok] = arg;
        g_gatew[tok] = 1.0f / s;
        atomicAdd(&g_counts[arg], 1);
    }
}
__global__ void k_scan() {
    if (threadIdx.x == 0) {
        int acc = 0; g_offsets[0] = 0;
        for (int e = 0; e < NEXP; e++) {
            acc += g_counts[e];
            g_offsets[e + 1] = acc;
            g_cursor[e] = g_offsets[e];
        }
    }
}
__global__ void k_scatter() {
    int tok = blockIdx.x * blockDim.x + threadIdx.x;
    if (tok >= NTOK) return;
    int slot = atomicAdd(&g_cursor[g_expert[tok]], 1);
    g_perm[slot] = tok;
}

// ================= HMMA grouped GEMM, on-the-fly bf16 hi/lo split =================
// BM=128, BN=128, BK=32 (fp32 sources). Smem: 4 bf16 tiles (A_hi,A_lo,B_hi,B_lo),
// 80B padded rows (conflict-free stores AND ldmatrix). Register-prefetch double
// buffering; fragments via ldmatrix.x4. 8 warps (4M x 2N), warp tile 32x64.
// Per k-tile: acc += Ahi*Bhi + Alo*Bhi + Ahi*Blo.
#define ROWB 80
#define AHI 0
#define ALO 10240
#define BHI 20480
#define BLO 30720

template <bool IS2>
__global__ __launch_bounds__(256) void k_ffn_mma(const float* __restrict__ W,
                                                 const float* __restrict__ bias,
                                                 const float* __restrict__ x,
                                                 float* __restrict__ y) {
    constexpr int K  = IS2 ? DHID : DMODEL;
    constexpr int NN = IS2 ? DMODEL : DHID;
    constexpr int KT = K / 32;

    __shared__ __align__(16) char smemc[40960];

    int e = blockIdx.z;
    int off = g_offsets[e];
    int cnt = g_offsets[e + 1] - off;
    int row0 = blockIdx.y * 128;
    if (row0 >= cnt) return;
    int col0 = blockIdx.x * 128;

    int tid = threadIdx.x, lane = tid & 31, wid = tid >> 5;
    int wm = wid & 3, wn = wid >> 2;
    int g = lane >> 2, q = lane & 3;
    uint32_t sb = smem_u32(smemc);

    // ---- per-thread staging assignments ----
    const float* arow[4]; uint32_t asw[4];
    const float* brow[4]; uint32_t bsw[4];
#pragma unroll
    for (int t = 0; t < 4; t++) {
        int c = tid + t * 256;
        int row = c >> 3, c8 = c & 7;
        int slot = off + row0 + row; if (slot > NTOK - 1) slot = NTOK - 1;
        if (IS2) arow[t] = g_h + (size_t)slot * DHID + c8 * 4;
        else     arow[t] = x + (size_t)g_perm[slot] * DMODEL + c8 * 4;
        asw[t] = (uint32_t)(row * ROWB + c8 * 8);
        int n = c & 127, k4 = c >> 7;
        brow[t] = W + (size_t)e * K * NN + (size_t)(k4 * 4) * NN + col0 + n;
        bsw[t] = (uint32_t)(n * ROWB + k4 * 8);
    }

    // ---- ldmatrix lane addresses (k16-independent parts) ----
    // A x4 tile (m16 x k16) at mtile mt: lane L -> row mb+(L&7)+8*((L>>3)&1), +16B if L>=16
    uint32_t aAddr[2];
#pragma unroll
    for (int mt = 0; mt < 2; mt++) {
        int mb = wm * 32 + mt * 16;
        int r = mb + (lane & 7) + 8 * ((lane >> 3) & 1);
        aAddr[mt] = sb + (uint32_t)(r * ROWB + (lane >> 4) * 16);
    }
    // B x4 covers n8-pair p (rows nb..nb+15): lane L -> n = nb+(L&7)+8*(L>>4), +16B if (L>>3)&1
    uint32_t bAddr[4];
#pragma unroll
    for (int p = 0; p < 4; p++) {
        int nb = wn * 64 + p * 16;
        int n = nb + (lane & 7) + 8 * (lane >> 4);
        bAddr[p] = sb + (uint32_t)(n * ROWB + ((lane >> 3) & 1) * 16);
    }

    float acc[2][8][4];
#pragma unroll
    for (int i = 0; i < 2; i++)
#pragma unroll
        for (int j = 0; j < 8; j++)
#pragma unroll
            for (int p = 0; p < 4; p++) acc[i][j][p] = 0.f;

    float4 fa[4];
    float fb[4][4];
#pragma unroll
    for (int t = 0; t < 4; t++) {
        fa[t] = *(const float4*)(arow[t]);
#pragma unroll
        for (int j = 0; j < 4; j++) fb[t][j] = brow[t][(size_t)j * NN];
    }

    for (int kt = 0; kt < KT; kt++) {
        __syncthreads();
        // ---- store staged tile (fast split fp32 -> hi/lo bf16) ----
#pragma unroll
        for (int t = 0; t < 4; t++) {
            uint32_t h0, l0, h1, l1;
            split2(fa[t].x, fa[t].y, h0, l0);
            split2(fa[t].z, fa[t].w, h1, l1);
            uint2 u;
            u.x = h0; u.y = h1; *(uint2*)(smemc + AHI + asw[t]) = u;
            u.x = l0; u.y = l1; *(uint2*)(smemc + ALO + asw[t]) = u;
            split2(fb[t][0], fb[t][1], h0, l0);
            split2(fb[t][2], fb[t][3], h1, l1);
            u.x = h0; u.y = h1; *(uint2*)(smemc + BHI + bsw[t]) = u;
            u.x = l0; u.y = l1; *(uint2*)(smemc + BLO + bsw[t]) = u;
        }
        __syncthreads();
        // ---- prefetch next k-tile ----
        if (kt + 1 < KT) {
            int kk = (kt + 1) * 32;
#pragma unroll
            for (int t = 0; t < 4; t++) {
                fa[t] = *(const float4*)(arow[t] + kk);
#pragma unroll
                for (int j = 0; j < 4; j++) fb[t][j] = brow[t][(size_t)(kk + j) * NN];
            }
        }
        // ---- compute ----
#pragma unroll
        for (int k16 = 0; k16 < 2; k16++) {
            uint32_t ko = (uint32_t)(k16 * 32);
            uint32_t ah[2][4], al[2][4];
#pragma unroll
            for (int mt = 0; mt < 2; mt++) {
                ldsm_x4(aAddr[mt] + AHI + ko, ah[mt][0], ah[mt][1], ah[mt][2], ah[mt][3]);
                ldsm_x4(aAddr[mt] + ALO + ko, al[mt][0], al[mt][1], al[mt][2], al[mt][3]);
            }
#pragma unroll
            for (int p = 0; p < 4; p++) {
                uint32_t bh0, bh1, bh2, bh3, bl0, bl1, bl2, bl3;
                ldsm_x4(bAddr[p] + BHI + ko, bh0, bh1, bh2, bh3);
                ldsm_x4(bAddr[p] + BLO + ko, bl0, bl1, bl2, bl3);
                int n0 = p * 2, n1 = p * 2 + 1;
                mma16816(acc[0][n0], ah[0], bh0, bh1);
                mma16816(acc[1][n0], ah[1], bh0, bh1);
                mma16816(acc[0][n0], al[0], bh0, bh1);
                mma16816(acc[1][n0], al[1], bh0, bh1);
                mma16816(acc[0][n0], ah[0], bl0, bl1);
                mma16816(acc[1][n0], ah[1], bl0, bl1);
                mma16816(acc[0][n1], ah[0], bh2, bh3);
                mma16816(acc[1][n1], ah[1], bh2, bh3);
                mma16816(acc[0][n1], al[0], bh2, bh3);
                mma16816(acc[1][n1], al[1], bh2, bh3);
                mma16816(acc[0][n1], ah[0], bl2, bl3);
                mma16816(acc[1][n1], ah[1], bl2, bl3);
            }
        }
    }

    // ================= epilogue =================
    const float* be_ = bias + (size_t)e * NN;
    int q2 = q * 2;
#pragma unroll
    for (int mt = 0; mt < 2; mt++) {
#pragma unroll
        for (int half = 0; half < 2; half++) {
            int ml = wm * 32 + mt * 16 + g + half * 8;
            if (row0 + ml >= cnt) continue;
            int slot = off + row0 + ml;
            if (!IS2) {
                float* hrow = g_h + (size_t)slot * DHID;
#pragma unroll
                for (int nt8 = 0; nt8 < 8; nt8++) {
                    int cg = col0 + wn * 64 + nt8 * 8 + q2;
                    float z0 = acc[mt][nt8][half * 2 + 0] + be_[cg];
                    float z1 = acc[mt][nt8][half * 2 + 1] + be_[cg + 1];
                    float2 o;
                    o.x = z0 / (1.f + expf(-z0));
                    o.y = z1 / (1.f + expf(-z1));
                    *(float2*)(hrow + cg) = o;
                }
            } else {
                int tok = g_perm[slot];
                float gw = g_gatew[tok];
                float* yrow = y + (size_t)tok * DMODEL;
#pragma unroll
                for (int nt8 = 0; nt8 < 8; nt8++) {
                    int cg = col0 + wn * 64 + nt8 * 8 + q2;
                    float2 o;
                    o.x = (acc[mt][nt8][half * 2 + 0] + be_[cg]) * gw;
                    o.y = (acc[mt][nt8][half * 2 + 1] + be_[cg + 1]) * gw;
                    *(float2*)(yrow + cg) = o;
                }
            }
        }
    }
}

// ================= launch =================
extern "C" void kernel_launch(void* const* d_in, const int* in_sizes, int n_in,
                              void* d_out, int out_size) {
    const float* x  = (const float*)d_in[0];
    const float* Wg = (const float*)d_in[1];
    const float* bg = (const float*)d_in[2];
    const float* W1 = (const float*)d_in[3];
    const float* b1 = (const float*)d_in[4];
    const float* W2 = (const float*)d_in[5];
    const float* b2 = (const float*)d_in[6];
    float* y = (float*)d_out;

    k_zero<<<1, 32>>>();
    k_gate<<<NTOK / 8, 256>>>(x, Wg, bg);
    k_scan<<<1, 1>>>();
    k_scatter<<<NTOK / 256, 256>>>();
    k_ffn_mma<false><<<dim3(DHID / 128, NTOK / 128, NEXP), 256>>>(W1, b1, x, nullptr);
    k_ffn_mma<true ><<<dim3(DMODEL / 128, NTOK / 128, NEXP), 256>>>(W2, b2, x, y);
}

// round 8
// speedup vs baseline: 2.5764x; 1.1936x over previous
#include <cuda_runtime.h>
#include <cuda_bf16.h>
#include <math.h>
#include <stdint.h>

#define NTOK 4096
#define DMODEL 1024
#define DHID 4096
#define NEXP 8

// ================= scratch (device globals: allocation-free) =================
__device__ int   g_expert[NTOK];
__device__ float g_gatew[NTOK];
__device__ int   g_counts[NEXP];
__device__ int   g_offsets[NEXP + 1];
__device__ int   g_cursor[NEXP];
__device__ int   g_perm[NTOK];
// grouped hidden, pre-split: [slot][0..DHID)=hi bf16, [DHID..2*DHID)=lo bf16 (64MB)
__device__ __align__(256) __nv_bfloat16 g_h[(size_t)NTOK * 2 * DHID];

__device__ __forceinline__ uint32_t smem_u32(const void* p) {
    uint32_t a;
    asm("{ .reg .u64 t; cvta.to.shared.u64 t, %1; cvt.u32.u64 %0, t; }" : "=r"(a) : "l"(p));
    return a;
}
__device__ __forceinline__ void mma16816(float* d, const uint32_t* a, uint32_t b0, uint32_t b1) {
    asm volatile("mma.sync.aligned.m16n8k16.row.col.f32.bf16.bf16.f32 "
        "{%0,%1,%2,%3}, {%4,%5,%6,%7}, {%8,%9}, {%0,%1,%2,%3};"
        : "+f"(d[0]), "+f"(d[1]), "+f"(d[2]), "+f"(d[3])
        : "r"(a[0]), "r"(a[1]), "r"(a[2]), "r"(a[3]), "r"(b0), "r"(b1));
}
__device__ __forceinline__ void ldsm_x4(uint32_t a, uint32_t& r0, uint32_t& r1,
                                        uint32_t& r2, uint32_t& r3) {
    asm volatile("ldmatrix.sync.aligned.m8n8.x4.shared.b16 {%0,%1,%2,%3}, [%4];"
        : "=r"(r0), "=r"(r1), "=r"(r2), "=r"(r3) : "r"(a));
}
// fast split: hi = truncate-to-bf16 (bit pack), lo = exact residual RN to bf16x2.
__device__ __forceinline__ void split2(float f0, float f1, uint32_t& hi, uint32_t& lo) {
    uint32_t u0 = __float_as_uint(f0), u1 = __float_as_uint(f1);
    hi = __byte_perm(u0, u1, 0x7632);
    float r0 = f0 - __uint_as_float(u0 & 0xFFFF0000u);
    float r1 = f1 - __uint_as_float(u1 & 0xFFFF0000u);
    __nv_bfloat162 p = __floats2bfloat162_rn(r0, r1);
    lo = *(uint32_t*)&p;
}

// ================= gating / routing (R1-proven) =================
__global__ void k_zero() {
    int t = threadIdx.x;
    if (t < NEXP) { g_counts[t] = 0; g_cursor[t] = 0; }
}
__global__ void k_gate(const float* __restrict__ x, const float* __restrict__ Wg,
                       const float* __restrict__ bg) {
    int tok = blockIdx.x * 8 + (threadIdx.x >> 5);
    int lane = threadIdx.x & 31;
    if (tok >= NTOK) return;
    float acc[NEXP];
#pragma unroll
    for (int e = 0; e < NEXP; e++) acc[e] = 0.f;
    const float* xr = x + (size_t)tok * DMODEL;
    for (int d = lane; d < DMODEL; d += 32) {
        float xv = xr[d];
        const float* wr = Wg + d * NEXP;
#pragma unroll
        for (int e = 0; e < NEXP; e++) acc[e] += xv * wr[e];
    }
#pragma unroll
    for (int e = 0; e < NEXP; e++)
#pragma unroll
        for (int o = 16; o > 0; o >>= 1) acc[e] += __shfl_xor_sync(0xffffffffu, acc[e], o);
    if (lane == 0) {
        float m = -1e30f; int arg = 0;
#pragma unroll
        for (int e = 0; e < NEXP; e++) {
            float l = acc[e] + bg[e]; acc[e] = l;
            if (l > m) { m = l; arg = e; }
        }
        float s = 0.f;
#pragma unroll
        for (int e = 0; e < NEXP; e++) s += expf(acc[e] - m);
        g_expert[tok] = arg;
        g_gatew[tok] = 1.0f / s;
        atomicAdd(&g_counts[arg], 1);
    }
}
__global__ void k_scan() {
    if (threadIdx.x == 0) {
        int acc = 0; g_offsets[0] = 0;
        for (int e = 0; e < NEXP; e++) {
            acc += g_counts[e];
            g_offsets[e + 1] = acc;
            g_cursor[e] = g_offsets[e];
        }
    }
}
__global__ void k_scatter() {
    int tok = blockIdx.x * blockDim.x + threadIdx.x;
    if (tok >= NTOK) return;
    int slot = atomicAdd(&g_cursor[g_expert[tok]], 1);
    g_perm[slot] = tok;
}

// ================= HMMA grouped GEMM, 2-stage pipeline =================
// BM=128, BN=128, BK=16 per stage, 2 stages in 48KB static smem.
// Row stride 48B (16 bf16 + 16B pad): ldmatrix conflict-free (3 coprime 8).
// Per stage: acc += Ahi*Bhi + Alo*Bhi + Ahi*Blo (error-compensated).
// 8 warps (4M x 2N), warp tile 32x64.
#define ROWB 48
#define STAGE 24576
#define AHI 0
#define ALO 6144
#define BHI 12288
#define BLO 18432

template <bool IS2>
__global__ __launch_bounds__(256, 2) void k_ffn_mma(const float* __restrict__ W,
                                                    const float* __restrict__ bias,
                                                    const float* __restrict__ x,
                                                    float* __restrict__ y) {
    constexpr int K  = IS2 ? DHID : DMODEL;
    constexpr int NN = IS2 ? DMODEL : DHID;
    constexpr int S  = K / 16;

    __shared__ __align__(16) char smemc[49152];

    int e = blockIdx.z;
    int off = g_offsets[e];
    int cnt = g_offsets[e + 1] - off;
    int row0 = blockIdx.y * 128;
    if (row0 >= cnt) return;
    int col0 = blockIdx.x * 128;

    int tid = threadIdx.x, lane = tid & 31, wid = tid >> 5;
    int wm = wid & 3, wn = wid >> 2;
    int g = lane >> 2, q = lane & 3;
    uint32_t sb = smem_u32(smemc);

    // ---- staging assignments ----
    // A: row = tid>>1 (128 rows), kc = tid&1 (8-elem half of 16)
    int arw = tid >> 1, kc = tid & 1;
    int aslot = off + row0 + arw; if (aslot > NTOK - 1) aslot = NTOK - 1;
    const float*         ax = nullptr;
    const __nv_bfloat16* ah = nullptr;
    if (IS2) ah = g_h + (size_t)aslot * (2 * DHID) + kc * 8;
    else     ax = x + (size_t)g_perm[aslot] * DMODEL + kc * 8;
    uint32_t asm_off = (uint32_t)(arw * ROWB + kc * 16);
    // B: n = tid&127, kg = tid>>7 (8-elem half)
    int bn = tid & 127, kg = tid >> 7;
    const float* bw = W + (size_t)e * K * NN + col0 + bn;
    uint32_t bsm_off = (uint32_t)(bn * ROWB + kg * 16);

    // ---- ldmatrix lane address offsets (within a stage buffer) ----
    uint32_t arel[2];
#pragma unroll
    for (int mt = 0; mt < 2; mt++) {
        int r = wm * 32 + mt * 16 + (lane & 7) + 8 * ((lane >> 3) & 1);
        arel[mt] = (uint32_t)(r * ROWB + (lane >> 4) * 16);
    }
    uint32_t brel[4];
#pragma unroll
    for (int p = 0; p < 4; p++) {
        int n = wn * 64 + p * 16 + (lane & 7) + 8 * (lane >> 4);
        brel[p] = (uint32_t)(n * ROWB + ((lane >> 3) & 1) * 16);
    }

    float acc[2][8][4];
#pragma unroll
    for (int i = 0; i < 2; i++)
#pragma unroll
        for (int j = 0; j < 8; j++)
#pragma unroll
            for (int p = 0; p < 4; p++) acc[i][j][p] = 0.f;

    // staging registers
    float4 fa0, fa1;          // FFN1 A (8 fp32)
    uint4  uahi, ualo;        // FFN2 A (pre-split)
    float  fb[8];             // B (8 fp32, strided)

#define LDG_STAGE(GI) do {                                                     \
        int kk = (GI) * 16;                                                    \
        if (IS2) {                                                             \
            uahi = *(const uint4*)(ah + kk);                                   \
            ualo = *(const uint4*)(ah + DHID + kk);                            \
        } else {                                                               \
            fa0 = *(const float4*)(ax + kk);                                   \
            fa1 = *(const float4*)(ax + kk + 4);                               \
        }                                                                      \
        int kb = kk + kg * 8;                                                  \
        _Pragma("unroll")                                                      \
        for (int j = 0; j < 8; j++) fb[j] = bw[(size_t)(kb + j) * NN];         \
    } while (0)

#define STORE_STAGE(BUF) do {                                                  \
        char* s_ = smemc + (BUF) * STAGE;                                      \
        if (IS2) {                                                             \
            *(uint4*)(s_ + AHI + asm_off) = uahi;                              \
            *(uint4*)(s_ + ALO + asm_off) = ualo;                              \
        } else {                                                               \
            uint4 h_, l_;                                                      \
            split2(fa0.x, fa0.y, h_.x, l_.x);                                  \
            split2(fa0.z, fa0.w, h_.y, l_.y);                                  \
            split2(fa1.x, fa1.y, h_.z, l_.z);                                  \
            split2(fa1.z, fa1.w, h_.w, l_.w);                                  \
            *(uint4*)(s_ + AHI + asm_off) = h_;                                \
            *(uint4*)(s_ + ALO + asm_off) = l_;                                \
        }                                                                      \
        uint4 bh_, bl_;                                                        \
        split2(fb[0], fb[1], bh_.x, bl_.x);                                    \
        split2(fb[2], fb[3], bh_.y, bl_.y);                                    \
        split2(fb[4], fb[5], bh_.z, bl_.z);                                    \
        split2(fb[6], fb[7], bh_.w, bl_.w);                                    \
        *(uint4*)(s_ + BHI + bsm_off) = bh_;                                   \
        *(uint4*)(s_ + BLO + bsm_off) = bl_;                                   \
    } while (0)

    // prologue
    LDG_STAGE(0);
    STORE_STAGE(0);
    LDG_STAGE(1);
    __syncthreads();

    for (int gi = 0; gi < S; gi++) {
        uint32_t sbuf = sb + (uint32_t)(gi & 1) * STAGE;
        // ---- compute stage gi ----
        uint32_t ahf[2][4], alf[2][4];
#pragma unroll
        for (int mt = 0; mt < 2; mt++) {
            ldsm_x4(sbuf + AHI + arel[mt], ahf[mt][0], ahf[mt][1], ahf[mt][2], ahf[mt][3]);
            ldsm_x4(sbuf + ALO + arel[mt], alf[mt][0], alf[mt][1], alf[mt][2], alf[mt][3]);
        }
#pragma unroll
        for (int p = 0; p < 4; p++) {
            uint32_t bh0, bh1, bh2, bh3, bl0, bl1, bl2, bl3;
            ldsm_x4(sbuf + BHI + brel[p], bh0, bh1, bh2, bh3);
            ldsm_x4(sbuf + BLO + brel[p], bl0, bl1, bl2, bl3);
            int n0 = p * 2, n1 = p * 2 + 1;
            mma16816(acc[0][n0], ahf[0], bh0, bh1);
            mma16816(acc[1][n0], ahf[1], bh0, bh1);
            mma16816(acc[0][n1], ahf[0], bh2, bh3);
            mma16816(acc[1][n1], ahf[1], bh2, bh3);
            mma16816(acc[0][n0], alf[0], bh0, bh1);
            mma16816(acc[1][n0], alf[1], bh0, bh1);
            mma16816(acc[0][n1], alf[0], bh2, bh3);
            mma16816(acc[1][n1], alf[1], bh2, bh3);
            mma16816(acc[0][n0], ahf[0], bl0, bl1);
            mma16816(acc[1][n0], ahf[1], bl0, bl1);
            mma16816(acc[0][n1], ahf[0], bl2, bl3);
            mma16816(acc[1][n1], ahf[1], bl2, bl3);
        }
        // ---- stage gi+1: split+store into the other buffer ----
        if (gi + 1 < S) STORE_STAGE((gi + 1) & 1);
        // ---- prefetch stage gi+2 ----
        if (gi + 2 < S) LDG_STAGE(gi + 2);
        __syncthreads();
    }
#undef LDG_STAGE
#undef STORE_STAGE

    // ================= epilogue =================
    const float* be_ = bias + (size_t)e * NN;
    int q2 = q * 2;
#pragma unroll
    for (int mt = 0; mt < 2; mt++) {
#pragma unroll
        for (int half = 0; half < 2; half++) {
            int ml = wm * 32 + mt * 16 + g + half * 8;
            if (row0 + ml >= cnt) continue;
            int slot = off + row0 + ml;
            if (!IS2) {
                __nv_bfloat16* hrow = g_h + (size_t)slot * (2 * DHID);
#pragma unroll
                for (int nt8 = 0; nt8 < 8; nt8++) {
                    int cg = col0 + wn * 64 + nt8 * 8 + q2;
                    float z0 = acc[mt][nt8][half * 2 + 0] + be_[cg];
                    float z1 = acc[mt][nt8][half * 2 + 1] + be_[cg + 1];
                    float s0 = z0 / (1.f + expf(-z0));
                    float s1 = z1 / (1.f + expf(-z1));
                    uint32_t hiw, low;
                    split2(s0, s1, hiw, low);
                    *(uint32_t*)(hrow + cg) = hiw;
                    *(uint32_t*)(hrow + DHID + cg) = low;
                }
            } else {
                int tok = g_perm[slot];
                float gw = g_gatew[tok];
                float* yrow = y + (size_t)tok * DMODEL;
#pragma unroll
                for (int nt8 = 0; nt8 < 8; nt8++) {
                    int cg = col0 + wn * 64 + nt8 * 8 + q2;
                    float2 o;
                    o.x = (acc[mt][nt8][half * 2 + 0] + be_[cg]) * gw;
                    o.y = (acc[mt][nt8][half * 2 + 1] + be_[cg + 1]) * gw;
                    *(float2*)(yrow + cg) = o;
                }
            }
        }
    }
}

// ================= launch =================
extern "C" void kernel_launch(void* const* d_in, const int* in_sizes, int n_in,
                              void* d_out, int out_size) {
    const float* x  = (const float*)d_in[0];
    const float* Wg = (const float*)d_in[1];
    const float* bg = (const float*)d_in[2];
    const float* W1 = (const float*)d_in[3];
    const float* b1 = (const float*)d_in[4];
    const float* W2 = (const float*)d_in[5];
    const float* b2 = (const float*)d_in[6];
    float* y = (float*)d_out;

    k_zero<<<1, 32>>>();
    k_gate<<<NTOK / 8, 256>>>(x, Wg, bg);
    k_scan<<<1, 1>>>();
    k_scatter<<<NTOK / 256, 256>>>();
    k_ffn_mma<false><<<dim3(DHID / 128, NTOK / 128, NEXP), 256>>>(W1, b1, x, nullptr);
    k_ffn_mma<true ><<<dim3(DMODEL / 128, NTOK / 128, NEXP), 256>>>(W2, b2, x, y);
}